// round 17
// baseline (speedup 1.0000x reference)
#include <cuda_runtime.h>

// HCEN forward with PDL overlap:
//  K1: x stream (proven shape: 16x64 blocks, 256 thr, unroll-16, __ldcs),
//      atomicAdd batch sums into g_m. Calls
//      cudaTriggerProgrammaticLaunchCompletion() at the TOP so the dependent
//      tail kernel launches ~immediately.
//  K2 (launched with ProgrammaticStreamSerialization): starts DURING K1,
//      issues its 8 MB of W loads into registers (overlaps the 36us stream),
//      then cudaGridDependencySynchronize() until K1's g_m atomics are
//      visible, then G1 -> grid barrier -> zero g_m -> G2. Post-K1 tail is
//      pure compute (~4us). If PDL is not honored this degenerates to the
//      R10 sequential behavior (still correct).

#define BATCH 16
#define SEQ   4096
#define DIM   1024
#define NCHUNK 64
#define SCHUNK (SEQ / NCHUNK)   // 64
#define FB2   128               // tail grid (1 block/SM, co-resident)

// Device-global scratch (no allocation allowed).
__device__ float g_m[BATCH * DIM];       // 64 KB sum accumulator (K2 re-zeroes)
__device__ float g_enc[BATCH * DIM];     // 64 KB
__device__ volatile unsigned g_bar[1];   // zero-init; self-resetting
__device__ unsigned g_exit;

// ---------------------------------------------------------------------------
// K1: grid (16, 64), block 256. Block (b,c) sums rows [c*64, c*64+64) of
// batch b; thread t owns float4 column t. __ldcs: read-once, evict-first.
// ---------------------------------------------------------------------------
__global__ void mean_partial_kernel(const float* __restrict__ x) {
    // Let the dependent tail kernel launch right away (its W prefetch then
    // overlaps this kernel's 36us x stream).
    cudaTriggerProgrammaticLaunchCompletion();

    const int b = blockIdx.x;
    const int c = blockIdx.y;
    const int t = threadIdx.x;

    const float4* __restrict__ x4 =
        reinterpret_cast<const float4*>(x + ((size_t)b * SEQ + (size_t)c * SCHUNK) * DIM);

    float4 acc = make_float4(0.f, 0.f, 0.f, 0.f);
#pragma unroll 16
    for (int s = 0; s < SCHUNK; s++) {
        float4 v = __ldcs(&x4[(size_t)s * (DIM / 4) + t]);
        acc.x += v.x; acc.y += v.y; acc.z += v.z; acc.w += v.w;
    }

    float* gm = g_m + (size_t)b * DIM + (size_t)t * 4;
    atomicAdd(gm + 0, acc.x);
    atomicAdd(gm + 1, acc.y);
    atomicAdd(gm + 2, acc.z);
    atomicAdd(gm + 3, acc.w);
}

// ---------------------------------------------------------------------------
// Grid barrier across K2's 128 co-resident blocks (1/SM).
// ---------------------------------------------------------------------------
__device__ __forceinline__ void grid_barrier(int which) {
    __syncthreads();
    if (threadIdx.x == 0) {
        __threadfence();
        atomicAdd((unsigned*)&g_bar[which], 1u);
        while (g_bar[which] < FB2) { }
        __threadfence();
    }
    __syncthreads();
}

// ---------------------------------------------------------------------------
// K2: fused GEMM tail. grid 128, block 256 (8 warps). Warp w owns h=bid*8+w
// for the FULL pipeline (both layers, all 16 batches in two 8-batch halves).
//  start: Wenc row -> wr[8] regs, Wout row -> wo[8] regs (in flight while
//         K1 still streams x), then cudaGridDependencySynchronize().
// ---------------------------------------------------------------------------
__global__ void fused_tail_kernel(const float* __restrict__ Wenc,
                                  const float* __restrict__ benc,
                                  const float* __restrict__ Wout,
                                  const float* __restrict__ bout,
                                  float* __restrict__ dout) {
    __shared__ float4 smA[8 * (DIM / 4)];   // 32 KB A tile

    const int t    = threadIdx.x;
    const int w    = t >> 5;
    const int lane = t & 31;
    const int bid  = blockIdx.x;
    const int h    = bid * 8 + w;

    // ---- W burst into registers; overlaps K1 (we launched early via PDL).
    const float4* __restrict__ We4 =
        reinterpret_cast<const float4*>(Wenc) + (size_t)h * (DIM / 4);
    const float4* __restrict__ Wo4 =
        reinterpret_cast<const float4*>(Wout) + (size_t)h * (DIM / 4);
    float4 wr[8], wo[8];
#pragma unroll
    for (int i = 0; i < 8; i++) wr[i] = We4[lane + i * 32];
#pragma unroll
    for (int i = 0; i < 8; i++) wo[i] = Wo4[lane + i * 32];

    // ---- Wait for K1 completion (g_m atomics visible after this). ----
    cudaGridDependencySynchronize();

    // ---- (G1) enc = (g_m / SEQ) @ Wenc^T + benc ----
    {
        const float4* __restrict__ M4 = reinterpret_cast<const float4*>(g_m);
        const float bv  = benc[h];
        const float inv = 1.0f / (float)SEQ;
#pragma unroll
        for (int half = 0; half < 2; half++) {
#pragma unroll
            for (int i = 0; i < 8; i++) {
                float4 v = M4[(size_t)half * 2048 + t + i * 256];
                v.x *= inv; v.y *= inv; v.z *= inv; v.w *= inv;
                smA[t + i * 256] = v;
            }
            __syncthreads();

            float acc[8] = {0.f, 0.f, 0.f, 0.f, 0.f, 0.f, 0.f, 0.f};
#pragma unroll
            for (int i = 0; i < 8; i++) {
                const int j = lane + i * 32;
#pragma unroll
                for (int b = 0; b < 8; b++) {
                    const float4 a = smA[b * 256 + j];
                    acc[b] += wr[i].x * a.x + wr[i].y * a.y + wr[i].z * a.z + wr[i].w * a.w;
                }
            }
#pragma unroll
            for (int off = 16; off > 0; off >>= 1)
#pragma unroll
                for (int b = 0; b < 8; b++)
                    acc[b] += __shfl_down_sync(0xffffffffu, acc[b], off);
            if (lane == 0) {
#pragma unroll
                for (int b = 0; b < 8; b++)
                    g_enc[(size_t)(half * 8 + b) * DIM + h] = acc[b] + bv;
            }
            __syncthreads();
        }
    }

    grid_barrier(0);

    // ---- Reset own g_m slice for the next graph replay. ----
    if (t < 128)
        g_m[(size_t)bid * 128 + t] = 0.f;

    // ---- (G2) out = enc @ Wout^T + bout ----
    {
        const float4* __restrict__ E4 = reinterpret_cast<const float4*>(g_enc);
        const float bv = bout[h];
#pragma unroll
        for (int half = 0; half < 2; half++) {
#pragma unroll
            for (int i = 0; i < 8; i++)
                smA[t + i * 256] = E4[(size_t)half * 2048 + t + i * 256];
            __syncthreads();

            float acc[8] = {0.f, 0.f, 0.f, 0.f, 0.f, 0.f, 0.f, 0.f};
#pragma unroll
            for (int i = 0; i < 8; i++) {
                const int j = lane + i * 32;
#pragma unroll
                for (int b = 0; b < 8; b++) {
                    const float4 a = smA[b * 256 + j];
                    acc[b] += wo[i].x * a.x + wo[i].y * a.y + wo[i].z * a.z + wo[i].w * a.w;
                }
            }
#pragma unroll
            for (int off = 16; off > 0; off >>= 1)
#pragma unroll
                for (int b = 0; b < 8; b++)
                    acc[b] += __shfl_down_sync(0xffffffffu, acc[b], off);
            if (lane == 0) {
#pragma unroll
                for (int b = 0; b < 8; b++)
                    dout[(size_t)(half * 8 + b) * DIM + h] = acc[b] + bv;
            }
            __syncthreads();
        }
    }

    // ---- reset counters for next graph replay (last block out). ----
    if (t == 0) {
        unsigned old = atomicAdd(&g_exit, 1u);
        if (old == FB2 - 1) {
            g_bar[0] = 0;
            __threadfence();
            g_exit = 0;
        }
    }
}

extern "C" void kernel_launch(void* const* d_in, const int* in_sizes, int n_in,
                              void* d_out, int out_size) {
    const float* x     = (const float*)d_in[0];
    const float* W_enc = (const float*)d_in[1];
    const float* b_enc = (const float*)d_in[2];
    const float* W_out = (const float*)d_in[3];
    const float* b_out = (const float*)d_in[4];
    float* out = (float*)d_out;

    (void)in_sizes; (void)n_in; (void)out_size;

    // Primary kernel: normal launch on the capture stream.
    mean_partial_kernel<<<dim3(BATCH, NCHUNK), 256>>>(x);

    // Dependent kernel: programmatic stream serialization (PDL). Captured as
    // a graph edge; K2 may begin once K1's CTAs execute the trigger, and its
    // cudaGridDependencySynchronize() provides the real data dependency.
    cudaLaunchConfig_t cfg = {};
    cfg.gridDim  = dim3(FB2, 1, 1);
    cfg.blockDim = dim3(256, 1, 1);
    cfg.dynamicSmemBytes = 0;
    cfg.stream = 0;
    cudaLaunchAttribute attrs[1];
    attrs[0].id = cudaLaunchAttributeProgrammaticStreamSerialization;
    attrs[0].val.programmaticStreamSerializationAllowed = 1;
    cfg.attrs = attrs;
    cfg.numAttrs = 1;
    cudaLaunchKernelEx(&cfg, fused_tail_kernel, W_enc, b_enc, W_out, b_out, out);
}